// round 3
// baseline (speedup 1.0000x reference)
#include <cuda_runtime.h>
#include <cuda_fp16.h>
#include <cstdint>

// ---------------------------------------------------------------------------
// Shapes (fixed): x[4096,8192] fp32, qweight[1024,8192] i32, qzeros[64,1024],
// scales[64,8192] fp32, bias[8192] fp32 -> out[4096,8192] fp32.
// GEMM path: fp16 operands, fp32 accumulate via mma.sync.m16n8k16 (sm_80 ISA,
// legal on the harness's compute_103 virtual arch — tcgen05 is NOT).
// ---------------------------------------------------------------------------
#define TOKENS   4096
#define INF      8192
#define OUTF     8192
#define KCHUNK   64
#define KCHUNKS  128            // INF / KCHUNK
#define MT       32             // TOKENS / 128
#define NT       32             // OUTF / 256
#define A_TILE   16384          // 128 m-rows * 128B (64 fp16, K-major, SW128)
#define B_TILE   32768          // 256 n-rows * 128B
#define STAGE_BYTES (A_TILE + B_TILE)
#define NSTAGES  4
#define SMEM_DYN (NSTAGES * STAGE_BYTES + 1024)   // + align pad

// scratch: tile-major, pre-swizzled fp16 operands (device globals, no alloc)
__device__ __align__(1024) unsigned char g_xt[(size_t)MT * KCHUNKS * A_TILE]; // 64 MB
__device__ __align__(1024) unsigned char g_wt[(size_t)NT * KCHUNKS * B_TILE]; // 128 MB

// ---------------------------------------------------------------------------
// helpers
// ---------------------------------------------------------------------------
__device__ __forceinline__ uint32_t smem_to_u32(const void* p) {
    uint32_t a;
    asm("{ .reg .u64 t; cvta.to.shared.u64 t, %1; cvt.u32.u64 %0, t; }" : "=r"(a) : "l"(p));
    return a;
}

#define SWZ(o) ((o) ^ (((o) >> 3) & 0x70))

__device__ __forceinline__ void cp_async16(uint32_t dst, const void* src) {
    asm volatile("cp.async.cg.shared.global [%0], [%1], 16;" :: "r"(dst), "l"(src));
}
#define CP_COMMIT() asm volatile("cp.async.commit_group;" ::: "memory")
#define CP_WAIT(n)  asm volatile("cp.async.wait_group %0;" :: "n"(n) : "memory")

__device__ __forceinline__ void ldsm4(uint32_t& r0, uint32_t& r1, uint32_t& r2, uint32_t& r3,
                                      uint32_t addr) {
    asm volatile("ldmatrix.sync.aligned.m8n8.x4.shared.b16 {%0,%1,%2,%3}, [%4];"
        : "=r"(r0), "=r"(r1), "=r"(r2), "=r"(r3) : "r"(addr));
}

__device__ __forceinline__ void mma16816(float* c,
    uint32_t a0, uint32_t a1, uint32_t a2, uint32_t a3, uint32_t b0, uint32_t b1) {
    asm volatile("mma.sync.aligned.m16n8k16.row.col.f32.f16.f16.f32 "
        "{%0,%1,%2,%3}, {%4,%5,%6,%7}, {%8,%9}, {%0,%1,%2,%3};"
        : "+f"(c[0]), "+f"(c[1]), "+f"(c[2]), "+f"(c[3])
        : "r"(a0), "r"(a1), "r"(a2), "r"(a3), "r"(b0), "r"(b1));
}

union HU { unsigned u; __half2 h; };
__device__ __forceinline__ unsigned h2u(__half2 h) { HU t; t.h = h; return t.u; }
__device__ __forceinline__ __half2 u2h(unsigned u) { HU t; t.u = u; return t.h; }

// ---------------------------------------------------------------------------
// prep_x: fp32 -> fp16, tile-major SW128, k-octet permutation (k0,k4)(k1,k5)...
// grid (MT, KCHUNKS), 256 threads
// ---------------------------------------------------------------------------
__global__ void __launch_bounds__(256) prep_x_kernel(const float* __restrict__ x) {
    int mt = blockIdx.x;            // 0..31
    int kc = blockIdx.y;            // 0..127
    unsigned char* tile = g_xt + ((size_t)(mt * KCHUNKS + kc)) * A_TILE;
    const float* xrowbase = x + (size_t)mt * 128 * INF + (size_t)kc * KCHUNK;
    for (int u = threadIdx.x; u < 1024; u += 256) {   // 128 rows * 8 octets
        int row = u >> 3, oct = u & 7;
        const float4* p = (const float4*)(xrowbase + (size_t)row * INF + oct * 8);
        float4 a = p[0];
        float4 b = p[1];
        uint4 o;
        o.x = h2u(__floats2half2_rn(a.x, b.x));   // (k0, k4)
        o.y = h2u(__floats2half2_rn(a.y, b.y));   // (k1, k5)
        o.z = h2u(__floats2half2_rn(a.z, b.z));   // (k2, k6)
        o.w = h2u(__floats2half2_rn(a.w, b.w));   // (k3, k7)
        *(uint4*)(tile + SWZ(row * 128 + oct * 16)) = o;
    }
}

// ---------------------------------------------------------------------------
// prep_w: int4 unpack + dequant -> fp16, n-major K-contiguous tiles, SW128,
// same k-octet permutation. The fp16 math is EXACT until the final scale mul:
// (1024+w) - (1024+z+1) = w-z-1 with all integers exactly representable.
// grid (OUTF/256, INF/8) = (32, 1024), 256 threads
// ---------------------------------------------------------------------------
__global__ void __launch_bounds__(256) prep_w_kernel(
    const int* __restrict__ qw, const int* __restrict__ qz, const float* __restrict__ sc)
{
    int n  = blockIdx.x * 256 + threadIdx.x;   // 0..8191
    int kr = blockIdx.y;                       // packed k-octet row, 0..1023
    int kc  = kr >> 3;                         // 64-k chunk index
    int oct = kr & 7;                          // octet within chunk
    int g   = kr >> 4;                         // 128-k quant group

    unsigned q  = (unsigned)qw[(size_t)kr * OUTF + n];
    unsigned zq = (unsigned)qz[(size_t)g * (OUTF / 8) + (n >> 3)];
    unsigned z  = (zq >> ((n & 7) * 4)) & 0xF;
    unsigned zb = 0x6400u + z + 1u;            // fp16 bits of (1024 + z + 1), exact
    __half2 zh2 = u2h(zb | (zb << 16));
    __half2 sh2 = __float2half2_rn(sc[(size_t)g * OUTF + n]);

    const unsigned m = 0x000F000Fu, add = 0x64006400u;
    unsigned v0 = (q & m) | add;               // (1024+k0, 1024+k4)
    unsigned v1 = ((q >> 4) & m) | add;        // (k1, k5)
    unsigned v2 = ((q >> 8) & m) | add;        // (k2, k6)
    unsigned v3 = ((q >> 12) & m) | add;       // (k3, k7)
    uint4 o;
    o.x = h2u(__hmul2(__hsub2(u2h(v0), zh2), sh2));
    o.y = h2u(__hmul2(__hsub2(u2h(v1), zh2), sh2));
    o.z = h2u(__hmul2(__hsub2(u2h(v2), zh2), sh2));
    o.w = h2u(__hmul2(__hsub2(u2h(v3), zh2), sh2));

    int nt = n >> 8;          // 256-wide n tile
    int rr = n & 255;         // n-row within tile
    unsigned char* tile = g_wt + ((size_t)(nt * KCHUNKS + kc)) * B_TILE;
    *(uint4*)(tile + SWZ(rr * 128 + oct * 16)) = o;
}

// ---------------------------------------------------------------------------
// gemm: 128M x 256N per CTA, 8 warps (2x4) of 64x64, K in 64-chunks,
// 4-stage cp.async pipeline, mma.sync m16n8k16 fp16->fp32.
// grid (MT, NT) = (32, 32), 256 threads
// ---------------------------------------------------------------------------
__global__ void __launch_bounds__(256, 1) gemm_kernel(
    const float* __restrict__ bias, float* __restrict__ out)
{
    extern __shared__ unsigned char smem_raw[];
    uint32_t base = (smem_to_u32(smem_raw) + 1023u) & ~1023u;

    int tid = threadIdx.x, wid = tid >> 5, lane = tid & 31;
    int wm = wid >> 2, wn = wid & 3;           // warp grid 2(m) x 4(n)
    int mt = blockIdx.x, nt = blockIdx.y;

    const unsigned char* gA = g_xt + (size_t)mt * KCHUNKS * A_TILE;
    const unsigned char* gB = g_wt + (size_t)nt * KCHUNKS * B_TILE;

    // cp.async stage fill: data is pre-swizzled in gmem -> verbatim 16B copies
    auto load_stage = [&](int chunk, int slot) {
        uint32_t sd = base + slot * STAGE_BYTES;
        const unsigned char* aS = gA + (size_t)chunk * A_TILE;
        const unsigned char* bS = gB + (size_t)chunk * B_TILE;
        #pragma unroll
        for (int i = 0; i < 4; i++)
            cp_async16(sd + (tid + 256 * i) * 16, aS + (size_t)(tid + 256 * i) * 16);
        #pragma unroll
        for (int i = 0; i < 8; i++)
            cp_async16(sd + A_TILE + (tid + 256 * i) * 16, bS + (size_t)(tid + 256 * i) * 16);
    };

    // ldmatrix per-lane geometry.
    // A x4 (per mb, per k16 step c): grp0=(rows mb16+0..7, oct 2c) -> a0,
    //  grp1=(+8, 2c)->a1, grp2=(0..7, 2c+1)->a2, grp3=(+8, 2c+1)->a3.
    // B x4 (per n-pair p, step c): grp0=(n 16p+0..7, 2c)->b0[2p],
    //  grp1=(same, 2c+1)->b1[2p], grp2=(+8, 2c)->b0[2p+1], grp3=(+8, 2c+1)->b1[2p+1].
    int gq = lane >> 3, r = lane & 7;
    int aRow0 = wm * 64 + (gq & 1) * 8 + r;   int aGh = gq >> 1;
    int bRow0 = wn * 64 + (gq >> 1) * 8 + r;  int bGl = gq & 1;

    float acc[4][8][4];
    #pragma unroll
    for (int i = 0; i < 4; i++)
        #pragma unroll
        for (int j = 0; j < 8; j++)
            #pragma unroll
            for (int k = 0; k < 4; k++) acc[i][j][k] = 0.f;

    // prologue: stages 0..2
    #pragma unroll
    for (int j = 0; j < NSTAGES - 1; j++) { load_stage(j, j); CP_COMMIT(); }

    #pragma unroll 1
    for (int it = 0; it < KCHUNKS; it++) {
        CP_WAIT(2);
        __syncthreads();
        if (it + NSTAGES - 1 < KCHUNKS) load_stage(it + NSTAGES - 1, (it + NSTAGES - 1) & 3);
        CP_COMMIT();

        uint32_t sA = base + (it & 3) * STAGE_BYTES;
        uint32_t sB = sA + A_TILE;
        #pragma unroll
        for (int c = 0; c < 4; c++) {                    // four k16 steps
            uint32_t a[4][4], b[4][4];
            #pragma unroll
            for (int mb = 0; mb < 4; mb++) {
                uint32_t off = (uint32_t)(aRow0 + mb * 16) * 128u
                             + (uint32_t)(((2 * c + aGh) ^ r) << 4);
                ldsm4(a[mb][0], a[mb][1], a[mb][2], a[mb][3], sA + off);
            }
            #pragma unroll
            for (int p = 0; p < 4; p++) {
                uint32_t off = (uint32_t)(bRow0 + p * 16) * 128u
                             + (uint32_t)(((2 * c + bGl) ^ r) << 4);
                ldsm4(b[p][0], b[p][1], b[p][2], b[p][3], sB + off);
            }
            #pragma unroll
            for (int mb = 0; mb < 4; mb++)
                #pragma unroll
                for (int p = 0; p < 4; p++) {
                    mma16816(acc[mb][2 * p],     a[mb][0], a[mb][1], a[mb][2], a[mb][3],
                             b[p][0], b[p][1]);
                    mma16816(acc[mb][2 * p + 1], a[mb][0], a[mb][1], a[mb][2], a[mb][3],
                             b[p][2], b[p][3]);
                }
        }
    }
    CP_WAIT(0);   // drain outstanding copies before exit

    // epilogue: acc frag (c0,c1)=(row l/4, col 2(l%4),+1), (c2,c3)=(row+8, same)
    int rowBase = mt * 128 + wm * 64 + (lane >> 2);
    int colBase = nt * 256 + wn * 64 + 2 * (lane & 3);
    #pragma unroll
    for (int nb = 0; nb < 8; nb++) {
        int n0 = colBase + nb * 8;
        float2 bv = *(const float2*)(bias + n0);
        #pragma unroll
        for (int mb = 0; mb < 4; mb++) {
            int m0 = rowBase + mb * 16;
            float2 v0 = { acc[mb][nb][0] + bv.x, acc[mb][nb][1] + bv.y };
            float2 v1 = { acc[mb][nb][2] + bv.x, acc[mb][nb][3] + bv.y };
            *(float2*)(out + (size_t)m0 * OUTF + n0) = v0;
            *(float2*)(out + (size_t)(m0 + 8) * OUTF + n0) = v1;
        }
    }
}

// ---------------------------------------------------------------------------
// launch
// ---------------------------------------------------------------------------
extern "C" void kernel_launch(void* const* d_in, const int* in_sizes, int n_in,
                              void* d_out, int out_size) {
    const float* x      = (const float*)d_in[0];
    const int*   qw     = (const int*)d_in[1];
    const int*   qz     = (const int*)d_in[2];
    const float* scales = (const float*)d_in[3];
    const float* bias   = (const float*)d_in[4];
    float* out = (float*)d_out;

    static int configured = 0;
    if (!configured) {
        cudaFuncSetAttribute(gemm_kernel, cudaFuncAttributeMaxDynamicSharedMemorySize, SMEM_DYN);
        configured = 1;
    }

    dim3 gx(MT, KCHUNKS);
    prep_x_kernel<<<gx, 256>>>(x);

    dim3 gw(OUTF / 256, INF / 8);
    prep_w_kernel<<<gw, 256>>>(qw, qz, scales);

    dim3 gg(MT, NT);
    gemm_kernel<<<gg, 256, SMEM_DYN>>>(bias, out);
}

// round 6
// speedup vs baseline: 1.1759x; 1.1759x over previous
#include <cuda_runtime.h>
#include <cuda_fp16.h>
#include <cstdint>

// ---------------------------------------------------------------------------
// Shapes (fixed): x[4096,8192] fp32, qweight[1024,8192] i32, qzeros[64,1024],
// scales[64,8192] fp32, bias[8192] fp32 -> out[4096,8192] fp32.
// GEMM path: fp16 operands, fp32 accumulate via mma.sync.m16n8k16 (sm_80 ISA,
// legal on the harness's compute_103 virtual arch — tcgen05 is NOT).
// ---------------------------------------------------------------------------
#define TOKENS   4096
#define INF      8192
#define OUTF     8192
#define KCHUNK   64
#define KCHUNKS  128            // INF / KCHUNK
#define MT       32             // TOKENS / 128
#define NT       32             // OUTF / 256
#define A_TILE   16384          // 128 m-rows * 128B (64 fp16, K-major, SW128)
#define B_TILE   32768          // 256 n-rows * 128B
#define STAGE_BYTES (A_TILE + B_TILE)
#define NSTAGES  4
#define SMEM_DYN (NSTAGES * STAGE_BYTES + 1024)   // + align pad

// scratch: tile-major, pre-swizzled fp16 operands (device globals, no alloc)
__device__ __align__(1024) unsigned char g_xt[(size_t)MT * KCHUNKS * A_TILE]; // 64 MB
__device__ __align__(1024) unsigned char g_wt[(size_t)NT * KCHUNKS * B_TILE]; // 128 MB

// ---------------------------------------------------------------------------
// helpers
// ---------------------------------------------------------------------------
__device__ __forceinline__ uint32_t smem_to_u32(const void* p) {
    uint32_t a;
    asm("{ .reg .u64 t; cvta.to.shared.u64 t, %1; cvt.u32.u64 %0, t; }" : "=r"(a) : "l"(p));
    return a;
}

#define SWZ(o) ((o) ^ (((o) >> 3) & 0x70))

__device__ __forceinline__ void cp_async16(uint32_t dst, const void* src) {
    asm volatile("cp.async.cg.shared.global [%0], [%1], 16;" :: "r"(dst), "l"(src));
}
#define CP_COMMIT() asm volatile("cp.async.commit_group;" ::: "memory")
#define CP_WAIT(n)  asm volatile("cp.async.wait_group %0;" :: "n"(n) : "memory")

__device__ __forceinline__ void ldsm4(uint32_t& r0, uint32_t& r1, uint32_t& r2, uint32_t& r3,
                                      uint32_t addr) {
    asm volatile("ldmatrix.sync.aligned.m8n8.x4.shared.b16 {%0,%1,%2,%3}, [%4];"
        : "=r"(r0), "=r"(r1), "=r"(r2), "=r"(r3) : "r"(addr));
}

__device__ __forceinline__ void mma16816(float* c,
    uint32_t a0, uint32_t a1, uint32_t a2, uint32_t a3, uint32_t b0, uint32_t b1) {
    asm volatile("mma.sync.aligned.m16n8k16.row.col.f32.f16.f16.f32 "
        "{%0,%1,%2,%3}, {%4,%5,%6,%7}, {%8,%9}, {%0,%1,%2,%3};"
        : "+f"(c[0]), "+f"(c[1]), "+f"(c[2]), "+f"(c[3])
        : "r"(a0), "r"(a1), "r"(a2), "r"(a3), "r"(b0), "r"(b1));
}

union HU { unsigned u; __half2 h; };
__device__ __forceinline__ unsigned h2u(__half2 h) { HU t; t.h = h; return t.u; }
__device__ __forceinline__ __half2 u2h(unsigned u) { HU t; t.u = u; return t.h; }

// ---------------------------------------------------------------------------
// prep_x: fp32 -> fp16, tile-major SW128, k-octet permutation (k0,k4)(k1,k5)...
// grid (MT, KCHUNKS), 256 threads
// ---------------------------------------------------------------------------
__global__ void __launch_bounds__(256) prep_x_kernel(const float* __restrict__ x) {
    int mt = blockIdx.x;            // 0..31
    int kc = blockIdx.y;            // 0..127
    unsigned char* tile = g_xt + ((size_t)(mt * KCHUNKS + kc)) * A_TILE;
    const float* xrowbase = x + (size_t)mt * 128 * INF + (size_t)kc * KCHUNK;
    for (int u = threadIdx.x; u < 1024; u += 256) {   // 128 rows * 8 octets
        int row = u >> 3, oct = u & 7;
        const float4* p = (const float4*)(xrowbase + (size_t)row * INF + oct * 8);
        float4 a = p[0];
        float4 b = p[1];
        uint4 o;
        o.x = h2u(__floats2half2_rn(a.x, b.x));   // (k0, k4)
        o.y = h2u(__floats2half2_rn(a.y, b.y));   // (k1, k5)
        o.z = h2u(__floats2half2_rn(a.z, b.z));   // (k2, k6)
        o.w = h2u(__floats2half2_rn(a.w, b.w));   // (k3, k7)
        *(uint4*)(tile + SWZ(row * 128 + oct * 16)) = o;
    }
}

// ---------------------------------------------------------------------------
// prep_w: int4 unpack + dequant -> fp16, n-major K-contiguous tiles, SW128,
// same k-octet permutation. The fp16 math is EXACT until the final scale mul:
// (1024+w) - (1024+z+1) = w-z-1 with all integers exactly representable.
// grid (OUTF/256, INF/8) = (32, 1024), 256 threads
// ---------------------------------------------------------------------------
__global__ void __launch_bounds__(256) prep_w_kernel(
    const int* __restrict__ qw, const int* __restrict__ qz, const float* __restrict__ sc)
{
    int n  = blockIdx.x * 256 + threadIdx.x;   // 0..8191
    int kr = blockIdx.y;                       // packed k-octet row, 0..1023
    int kc  = kr >> 3;                         // 64-k chunk index
    int oct = kr & 7;                          // octet within chunk
    int g   = kr >> 4;                         // 128-k quant group

    unsigned q  = (unsigned)qw[(size_t)kr * OUTF + n];
    unsigned zq = (unsigned)qz[(size_t)g * (OUTF / 8) + (n >> 3)];
    unsigned z  = (zq >> ((n & 7) * 4)) & 0xF;
    unsigned zb = 0x6400u + z + 1u;            // fp16 bits of (1024 + z + 1), exact
    __half2 zh2 = u2h(zb | (zb << 16));
    __half2 sh2 = __float2half2_rn(sc[(size_t)g * OUTF + n]);

    const unsigned m = 0x000F000Fu, add = 0x64006400u;
    unsigned v0 = (q & m) | add;               // (1024+k0, 1024+k4)
    unsigned v1 = ((q >> 4) & m) | add;        // (k1, k5)
    unsigned v2 = ((q >> 8) & m) | add;        // (k2, k6)
    unsigned v3 = ((q >> 12) & m) | add;       // (k3, k7)
    uint4 o;
    o.x = h2u(__hmul2(__hsub2(u2h(v0), zh2), sh2));
    o.y = h2u(__hmul2(__hsub2(u2h(v1), zh2), sh2));
    o.z = h2u(__hmul2(__hsub2(u2h(v2), zh2), sh2));
    o.w = h2u(__hmul2(__hsub2(u2h(v3), zh2), sh2));

    int nt = n >> 8;          // 256-wide n tile
    int rr = n & 255;         // n-row within tile
    unsigned char* tile = g_wt + ((size_t)(nt * KCHUNKS + kc)) * B_TILE;
    *(uint4*)(tile + SWZ(rr * 128 + oct * 16)) = o;
}

// ---------------------------------------------------------------------------
// gemm: 128M x 256N per CTA, 8 warps (2x4) of 64x64, K in 64-chunks,
// 4-stage cp.async pipeline, mma.sync m16n8k16 fp16->fp32.
// Register double-buffered ldmatrix fragments: prefetch step c+1 (and the
// next chunk's step 0 across the barrier) before issuing step c's MMAs.
// grid (MT, NT) = (32, 32), 256 threads
// ---------------------------------------------------------------------------
__global__ void __launch_bounds__(256, 1) gemm_kernel(
    const float* __restrict__ bias, float* __restrict__ out)
{
    extern __shared__ unsigned char smem_raw[];
    uint32_t base = (smem_to_u32(smem_raw) + 1023u) & ~1023u;

    int tid = threadIdx.x, wid = tid >> 5, lane = tid & 31;
    int wm = wid >> 2, wn = wid & 3;           // warp grid 2(m) x 4(n)
    int mt = blockIdx.x, nt = blockIdx.y;

    const unsigned char* gA = g_xt + (size_t)mt * KCHUNKS * A_TILE;
    const unsigned char* gB = g_wt + (size_t)nt * KCHUNKS * B_TILE;

    // cp.async stage fill: data is pre-swizzled in gmem -> verbatim 16B copies
    auto load_stage = [&](int chunk, int slot) {
        uint32_t sd = base + slot * STAGE_BYTES;
        const unsigned char* aS = gA + (size_t)chunk * A_TILE;
        const unsigned char* bS = gB + (size_t)chunk * B_TILE;
        #pragma unroll
        for (int i = 0; i < 4; i++)
            cp_async16(sd + (tid + 256 * i) * 16, aS + (size_t)(tid + 256 * i) * 16);
        #pragma unroll
        for (int i = 0; i < 8; i++)
            cp_async16(sd + A_TILE + (tid + 256 * i) * 16, bS + (size_t)(tid + 256 * i) * 16);
    };

    // ldmatrix per-lane geometry (validated in round 3).
    int gq = lane >> 3, r = lane & 7;
    int aRow0 = wm * 64 + (gq & 1) * 8 + r;   int aGh = gq >> 1;
    int bRow0 = wn * 64 + (gq >> 1) * 8 + r;  int bGl = gq & 1;

    float acc[4][8][4];
    #pragma unroll
    for (int i = 0; i < 4; i++)
        #pragma unroll
        for (int j = 0; j < 8; j++)
            #pragma unroll
            for (int k = 0; k < 4; k++) acc[i][j][k] = 0.f;

    // double-buffered fragments (all indices compile-time)
    uint32_t afr[2][4][4], bfr[2][4][4];

#define PREFETCH(BUF, BASE, C) do {                                               \
        uint32_t _sA = (BASE), _sB = (BASE) + A_TILE;                             \
        _Pragma("unroll")                                                         \
        for (int mb = 0; mb < 4; mb++) {                                          \
            uint32_t off = (uint32_t)(aRow0 + mb * 16) * 128u                     \
                         + (uint32_t)(((2 * (C) + aGh) ^ r) << 4);                \
            ldsm4(afr[BUF][mb][0], afr[BUF][mb][1], afr[BUF][mb][2],              \
                  afr[BUF][mb][3], _sA + off);                                    \
        }                                                                         \
        _Pragma("unroll")                                                         \
        for (int p = 0; p < 4; p++) {                                             \
            uint32_t off = (uint32_t)(bRow0 + p * 16) * 128u                      \
                         + (uint32_t)(((2 * (C) + bGl) ^ r) << 4);                \
            ldsm4(bfr[BUF][p][0], bfr[BUF][p][1], bfr[BUF][p][2],                 \
                  bfr[BUF][p][3], _sB + off);                                     \
        }                                                                         \
    } while (0)

#define MMASTEP(BUF) do {                                                         \
        _Pragma("unroll")                                                         \
        for (int mb = 0; mb < 4; mb++)                                            \
            _Pragma("unroll")                                                     \
            for (int p = 0; p < 4; p++) {                                         \
                mma16816(acc[mb][2 * p],     afr[BUF][mb][0], afr[BUF][mb][1],    \
                         afr[BUF][mb][2], afr[BUF][mb][3],                        \
                         bfr[BUF][p][0], bfr[BUF][p][1]);                         \
                mma16816(acc[mb][2 * p + 1], afr[BUF][mb][0], afr[BUF][mb][1],    \
                         afr[BUF][mb][2], afr[BUF][mb][3],                        \
                         bfr[BUF][p][2], bfr[BUF][p][3]);                         \
            }                                                                     \
    } while (0)

    // prologue: stages 0..2 in flight, then stage 0 ready -> preload step 0
    #pragma unroll
    for (int j = 0; j < NSTAGES - 1; j++) { load_stage(j, j); CP_COMMIT(); }
    CP_WAIT(2);
    __syncthreads();
    PREFETCH(0, base, 0);

    #pragma unroll 1
    for (int it = 0; it < KCHUNKS; it++) {
        // stages <= it+1 complete & visible after this barrier
        CP_WAIT(1);
        __syncthreads();
        if (it + NSTAGES - 1 < KCHUNKS) load_stage(it + NSTAGES - 1, (it + NSTAGES - 1) & 3);
        CP_COMMIT();

        uint32_t cbase = base + (it & 3) * STAGE_BYTES;
        uint32_t nbase = base + ((it + 1) & 3) * STAGE_BYTES;
        PREFETCH(1, cbase, 1); MMASTEP(0);
        PREFETCH(0, cbase, 2); MMASTEP(1);
        PREFETCH(1, cbase, 3); MMASTEP(0);
        PREFETCH(0, nbase, 0); MMASTEP(1);   // cross-chunk: next chunk's step 0
    }
    CP_WAIT(0);   // drain outstanding copies before exit

#undef PREFETCH
#undef MMASTEP

    // epilogue: acc frag (c0,c1)=(row l/4, col 2(l%4),+1), (c2,c3)=(row+8, same)
    int rowBase = mt * 128 + wm * 64 + (lane >> 2);
    int colBase = nt * 256 + wn * 64 + 2 * (lane & 3);
    #pragma unroll
    for (int nb = 0; nb < 8; nb++) {
        int n0 = colBase + nb * 8;
        float2 bv = *(const float2*)(bias + n0);
        #pragma unroll
        for (int mb = 0; mb < 4; mb++) {
            int m0 = rowBase + mb * 16;
            float2 v0 = { acc[mb][nb][0] + bv.x, acc[mb][nb][1] + bv.y };
            float2 v1 = { acc[mb][nb][2] + bv.x, acc[mb][nb][3] + bv.y };
            *(float2*)(out + (size_t)m0 * OUTF + n0) = v0;
            *(float2*)(out + (size_t)(m0 + 8) * OUTF + n0) = v1;
        }
    }
}

// ---------------------------------------------------------------------------
// launch
// ---------------------------------------------------------------------------
extern "C" void kernel_launch(void* const* d_in, const int* in_sizes, int n_in,
                              void* d_out, int out_size) {
    const float* x      = (const float*)d_in[0];
    const int*   qw     = (const int*)d_in[1];
    const int*   qz     = (const int*)d_in[2];
    const float* scales = (const float*)d_in[3];
    const float* bias   = (const float*)d_in[4];
    float* out = (float*)d_out;

    static int configured = 0;
    if (!configured) {
        cudaFuncSetAttribute(gemm_kernel, cudaFuncAttributeMaxDynamicSharedMemorySize, SMEM_DYN);
        configured = 1;
    }

    dim3 gx(MT, KCHUNKS);
    prep_x_kernel<<<gx, 256>>>(x);

    dim3 gw(OUTF / 256, INF / 8);
    prep_w_kernel<<<gw, 256>>>(qw, qz, scales);

    dim3 gg(MT, NT);
    gemm_kernel<<<gg, 256, SMEM_DYN>>>(bias, out);
}